// round 16
// baseline (speedup 1.0000x reference)
#include <cuda_runtime.h>
#include <cstdint>

// Tensor-train chain, fp32 f32x2, R16: 2 CTAs per SM anti-phase.
// TB=14 (7 pairs), 256 threads (8 warps = 4 l-quarters x 2 sg groups),
// grid=294 = 2 CTAs/SM. Single C buffer per CTA (64 KB); the exposed
// per-step C load window of one CTA is covered by the co-resident CTA's
// compute phase. C relayouted (R15) so k-loop uses LDS.128 only.

#define BATCH   4096
#define LEN     128
#define RANK    64
#define NSTEP   126
#define CSTEP   16384          // floats per mid-core step (64 KB)
#define TB      14             // batches per CTA (7 pairs)
#define NPAIR   7
#define GRID    294            // 294*14 = 4116 >= 4096
#define THREADS 256
#define VPITCH  66             // f32x2 per vbuf pair-row (64 + 2 pad)

// smem: Cbuf CSTEP floats (single buffer) | vbuf [7][VPITCH] f32x2
//       | scr [2][4][7][32] ull2 | xring [2][TB][4] floats
#define SCR_U2  (2*4*NPAIR*32)
#define SMEM_BYTES (CSTEP*4 + NPAIR*VPITCH*8 + SCR_U2*16 + 2*TB*4*4)

// relayouted mid-cores: 126 * 4096 float4 = 8.25 MB device scratch
__device__ float4 c_relay[NSTEP * 4096];

extern __shared__ float smem_f[];

__device__ __forceinline__ uint64_t fma2(uint64_t a, uint64_t b, uint64_t c) {
    uint64_t d;
    asm("fma.rn.f32x2 %0, %1, %2, %3;" : "=l"(d) : "l"(a), "l"(b), "l"(c));
    return d;
}
__device__ __forceinline__ uint64_t mul2(uint64_t a, uint64_t b) {
    uint64_t d;
    asm("mul.rn.f32x2 %0, %1, %2;" : "=l"(d) : "l"(a), "l"(b));
    return d;
}
__device__ __forceinline__ uint64_t dup2(float f) {
    uint64_t d;
    asm("mov.b64 %0, {%1, %1};" : "=l"(d) : "f"(f));
    return d;
}
__device__ __forceinline__ uint64_t pack2(float a, float b) {
    uint64_t d;
    asm("mov.b64 %0, {%1, %2};" : "=l"(d) : "f"(a), "f"(b));
    return d;
}
__device__ __forceinline__ uint32_t smem_u32(const void* p) {
    return (uint32_t)__cvta_generic_to_shared(p);
}
__device__ __forceinline__ void cp_async16(uint32_t dst, const void* src) {
    asm volatile("cp.async.cg.shared.global [%0], [%1], 16;\n" :: "r"(dst), "l"(src));
}

// ---- pre-pass: re-tile mid_cores into c_relay (same as R15) ----
__global__ void __launch_bounds__(256)
relayout_kernel(const float* __restrict__ mc)
{
    int d = blockIdx.x * 256 + threadIdx.x;        // 0 .. 126*4096-1
    if (d >= NSTEP * 4096) return;
    int rp = d & 31;
    int ih = (d >> 5) & 1;
    int l  = (d >> 6) & 63;
    int s  = d >> 12;
    const float* src = mc + ((size_t)(s * 64 + l) * 4 + 2 * ih) * 64 + 2 * rp;
    c_relay[d] = make_float4(src[0], src[1], src[64], src[65]);
}

// Step body (R15 math): one LDS.128 per (l, ihalf) feeds 4 dup2 + 4P fma2.
template<int P>
__device__ __forceinline__ void step_body(
    const float4* __restrict__ CsL, const float2* __restrict__ vrow,
    const float* __restrict__ xrp,
    ulonglong2* __restrict__ scrW, int lane)
{
    uint64_t t[4][P][2];
    #pragma unroll
    for (int i = 0; i < 4; ++i)
        #pragma unroll
        for (int p = 0; p < P; ++p) { t[i][p][0] = 0ull; t[i][p][1] = 0ull; }

    #pragma unroll
    for (int h = 0; h < 8; ++h) {
        const int l2 = 2 * h;
        uint64_t vA[P], vB[P];
        #pragma unroll
        for (int p = 0; p < P; ++p) {
            ulonglong2 V = *(const ulonglong2*)(vrow + p * VPITCH + l2);
            vA[p] = V.x;
            vB[p] = V.y;
        }
        #pragma unroll
        for (int li = 0; li < 2; ++li) {
            #pragma unroll
            for (int ih = 0; ih < 2; ++ih) {
                float4 c = CsL[((l2 + li) * 2 + ih) * 32];
                uint64_t c00 = dup2(c.x);
                uint64_t c01 = dup2(c.y);
                uint64_t c10 = dup2(c.z);
                uint64_t c11 = dup2(c.w);
                #pragma unroll
                for (int p = 0; p < P; ++p) {
                    uint64_t vv = li ? vB[p] : vA[p];
                    t[2*ih  ][p][0] = fma2(vv, c00, t[2*ih  ][p][0]);
                    t[2*ih  ][p][1] = fma2(vv, c01, t[2*ih  ][p][1]);
                    t[2*ih+1][p][0] = fma2(vv, c10, t[2*ih+1][p][0]);
                    t[2*ih+1][p][1] = fma2(vv, c11, t[2*ih+1][p][1]);
                }
            }
        }
    }

    #pragma unroll
    for (int p = 0; p < P; ++p) {
        float4 xa = *(const float4*)(xrp + p * 8);
        float4 xb = *(const float4*)(xrp + p * 8 + 4);
        uint64_t xp0 = pack2(xa.x, xb.x);
        uint64_t xp1 = pack2(xa.y, xb.y);
        uint64_t xp2 = pack2(xa.z, xb.z);
        uint64_t xp3 = pack2(xa.w, xb.w);
        uint64_t n0 = mul2(xp0, t[0][p][0]);
        n0 = fma2(xp1, t[1][p][0], n0);
        n0 = fma2(xp2, t[2][p][0], n0);
        n0 = fma2(xp3, t[3][p][0], n0);
        uint64_t n1 = mul2(xp0, t[0][p][1]);
        n1 = fma2(xp1, t[1][p][1], n1);
        n1 = fma2(xp2, t[2][p][1], n1);
        n1 = fma2(xp3, t[3][p][1], n1);
        ulonglong2 w; w.x = n0; w.y = n1;
        scrW[p * 32 + lane] = w;
    }
}

__global__ void __launch_bounds__(THREADS, 2)
tt_chain_kernel(const float* __restrict__ x,    // [B, 128, 4]
                const float* __restrict__ fc,   // [4, 64]
                const float* __restrict__ lc,   // [64, 4]
                float* __restrict__ out)        // [B, 1]
{
    float*      Cbuf = smem_f;                             // single buffer
    float2*     vbuf = (float2*)(smem_f + CSTEP);          // [7][VPITCH]
    ulonglong2* scr  = (ulonglong2*)(vbuf + NPAIR*VPITCH); // [2][4][7][32]
    float2*     scrf = (float2*)scr;                        // f2 view
    float2*     epi  = (float2*)scr;                        // parity-0 alias
    float*      xs   = (float*)(scr + SCR_U2);              // [2][TB][4]

    const float* mcr = (const float*)c_relay;

    const int tid  = threadIdx.x;
    const int warp = tid >> 5;
    const int lane = tid & 31;
    const int q    = warp & 3;             // l-quarter AND SMSP id
    const int sg   = warp >> 2;            // pair group (0: 4 pairs, 1: 3)
    const int Pw   = sg ? 3 : 4;
    const int base = sg ? 4 : 0;

    // ---- prologue: issue C[0] + x(1) ----
    {
        uint32_t dst = smem_u32(Cbuf);
        #pragma unroll
        for (int j = 0; j < 16; ++j) {
            int idx = j * THREADS + tid;           // 4096 16B chunks
            cp_async16(dst + idx * 16, mcr + idx * 4);
        }
        if (tid < TB) {
            int gb = blockIdx.x * TB + tid;
            if (gb > BATCH - 1) gb = BATCH - 1;
            cp_async16(smem_u32(xs + 1 * (TB * 4) + tid * 4),
                       x + (size_t)gb * (LEN * 4) + 1 * 4);
        }
        asm volatile("cp.async.commit_group;\n");
    }

    // ---- v0 into warp-private vbuf slots ----
    #pragma unroll
    for (int v = 0; v < 2; ++v) {
        int slot = lane + 32 * v;
        int pi = slot >> 4;
        int ro = slot & 15;
        if (pi < Pw) {
            int l = 16 * q + ro;
            int b0 = blockIdx.x * TB + 2 * (base + pi);
            int b1 = b0 + 1;
            if (b0 > BATCH - 1) b0 = BATCH - 1;
            if (b1 > BATCH - 1) b1 = BATCH - 1;
            float4 xA = *(const float4*)(x + (size_t)b0 * (LEN * 4));
            float4 xB = *(const float4*)(x + (size_t)b1 * (LEN * 4));
            float f0 = fc[l], f1 = fc[64 + l], f2 = fc[128 + l], f3 = fc[192 + l];
            float vx = f0*xA.x + f1*xA.y + f2*xA.z + f3*xA.w;
            float vy = f0*xB.x + f1*xB.y + f2*xB.z + f3*xB.w;
            vbuf[(base + pi) * VPITCH + l] = make_float2(vx, vy);
        }
    }
    asm volatile("cp.async.wait_group 0;\n");
    __syncthreads();   // C[0], x(1) visible CTA-wide; vbuf warp-private

    // ---- main chain ----
    #pragma unroll 1
    for (int s = 0; s < NSTEP; ++s) {
        // k-loop on C[s] (resident in the single buffer)
        {
            const float4* CsL = (const float4*)Cbuf + (size_t)(1024 * q) + lane;
            const float2* vrow = vbuf + base * VPITCH + 16 * q;
            const float* xrp = xs + ((s + 1) & 1) * (TB * 4) + base * 8;
            ulonglong2* scrW = scr + (size_t)(((s & 1) * 4 + q) * NPAIR + base) * 32;
            if (Pw == 4) step_body<4>(CsL, vrow, xrp, scrW, lane);
            else         step_body<3>(CsL, vrow, xrp, scrW, lane);
        }

        __syncthreads();   // all reads of C[s] done; scr par s&1 complete

        // issue C[s+1] into the (now free) buffer + x(s+2) staging
        if (s + 1 < NSTEP) {
            uint32_t dst = smem_u32(Cbuf);
            const float* src = mcr + (size_t)(s + 1) * CSTEP;
            #pragma unroll
            for (int j = 0; j < 16; ++j) {
                int idx = j * THREADS + tid;
                cp_async16(dst + idx * 16, src + idx * 4);
            }
        }
        if (s + 2 <= LEN - 1 && tid < TB) {
            int gb = blockIdx.x * TB + tid;
            if (gb > BATCH - 1) gb = BATCH - 1;
            cp_async16(smem_u32(xs + ((s + 2) & 1) * (TB * 4) + tid * 4),
                       x + (size_t)gb * (LEN * 4) + (size_t)(s + 2) * 4);
        }
        asm volatile("cp.async.commit_group;\n");

        // finalize v_{s+1} from scr par s&1 (no C needed — runs in load window)
        {
            const int par = s & 1;
            #pragma unroll
            for (int v = 0; v < 2; ++v) {
                int slot = lane + 32 * v;
                int pi = slot >> 4;
                int ro = slot & 15;
                if (pi < Pw) {
                    int pb = base + pi;
                    int l  = 16 * q + ro;
                    const float2* sp = scrf + (size_t)((par * 4) * NPAIR + pb) * 64 + l;
                    float2 a = sp[0];
                    float2 b = sp[NPAIR * 64];
                    float2 c = sp[2 * NPAIR * 64];
                    float2 d = sp[3 * NPAIR * 64];
                    vbuf[pb * VPITCH + l] =
                        make_float2((a.x + b.x) + (c.x + d.x),
                                    (a.y + b.y) + (c.y + d.y));
                }
            }
        }
        __syncwarp();

        asm volatile("cp.async.wait_group 0;\n");   // own C[s+1] chunks landed
        __syncthreads();                            // C[s+1] visible CTA-wide
    }

    // ---- epilogue: v_126 is in vbuf (finalize@125); dot with last-site vector ----
    {
        const float* xr127 = xs + 1 * (TB * 4);     // site 127, slot 1
        #pragma unroll
        for (int v = 0; v < 2; ++v) {
            int slot = lane + 32 * v;
            int pi = slot >> 4;
            int ro = slot & 15;
            float2 contrib = make_float2(0.f, 0.f);
            int valid = (pi < Pw);
            int pb = base + (valid ? pi : 0);
            if (valid) {
                int l = 16 * q + ro;
                float2 vv = vbuf[pb * VPITCH + l];
                float4 l4  = *(const float4*)(lc + l * 4);
                float4 xe0 = *(const float4*)(xr127 + (2 * pb) * 4);
                float4 xe1 = *(const float4*)(xr127 + (2 * pb + 1) * 4);
                float lva = l4.x*xe0.x + l4.y*xe0.y + l4.z*xe0.z + l4.w*xe0.w;
                float lvb = l4.x*xe1.x + l4.y*xe1.y + l4.z*xe1.z + l4.w*xe1.w;
                contrib = make_float2(vv.x * lva, vv.y * lvb);
            }
            #pragma unroll
            for (int off = 8; off > 0; off >>= 1) {
                contrib.x += __shfl_down_sync(0xffffffffu, contrib.x, off, 16);
                contrib.y += __shfl_down_sync(0xffffffffu, contrib.y, off, 16);
            }
            __syncwarp();
            if (ro == 0 && valid)
                epi[q * NPAIR + pb] = contrib;   // parity-0 alias region
        }
    }
    __syncthreads();
    if (tid < TB) {
        int b = blockIdx.x * TB + tid;
        if (b < BATCH) {
            int pb = tid >> 1;
            float sum = 0.f;
            #pragma unroll
            for (int qq = 0; qq < 4; ++qq) {
                float2 e = epi[qq * NPAIR + pb];
                sum += (tid & 1) ? e.y : e.x;
            }
            out[b] = sum;
        }
    }
}

extern "C" void kernel_launch(void* const* d_in, const int* in_sizes, int n_in,
                              void* d_out, int out_size) {
    const float* x  = (const float*)d_in[0];   // input_data [4096,128,4]
    const float* fc = (const float*)d_in[1];   // first_core [4,64]
    const float* mc = (const float*)d_in[2];   // mid_cores  [126,64,4,64]
    const float* lc = (const float*)d_in[3];   // last_core  [64,4]
    float* out = (float*)d_out;

    cudaFuncSetAttribute(tt_chain_kernel,
                         cudaFuncAttributeMaxDynamicSharedMemorySize, SMEM_BYTES);

    // pre-pass: re-tile mid_cores (8.25 MB, ~3 us)
    relayout_kernel<<<(NSTEP * 4096 + 255) / 256, 256>>>(mc);
    tt_chain_kernel<<<GRID, THREADS, SMEM_BYTES>>>(x, fc, lc, out);
}

// round 17
// speedup vs baseline: 1.8247x; 1.8247x over previous
#include <cuda_runtime.h>
#include <cstdint>

// Tensor-train chain, fp32 f32x2, TB=28/grid=147 (R15 base = best 371.4us).
// R17: 384 threads = 12 warps = 4 l-quarters x 3 sg groups (P = {5,5,4}).
// Cuts C crossbar traffic 25% (12 instead of 16 warps re-read each quarter)
// and dup2/issue count, at the cost of 3 warps/SMSP latency hiding.
// C relayouted for LDS.128-only k-loop (R15); x smem ring (R12).

#define BATCH   4096
#define LEN     128
#define RANK    64
#define NSTEP   126
#define CSTEP   16384          // floats per mid-core step
#define TB      28             // batches per CTA (14 pairs)
#define NPAIR   14
#define GRID    147            // 147*28 = 4116 >= 4096
#define THREADS 384            // 12 warps
#define VPITCH  66             // f32x2 per vbuf pair-row (64 + 2 pad)

// smem: Cbuf 2*CSTEP floats | vbuf [14][VPITCH] f32x2 | scr [2][4][14][32] ull2
//       | xring [2][TB][4] floats
#define SCR_U2  (2*4*NPAIR*32)
#define SMEM_BYTES (2*CSTEP*4 + NPAIR*VPITCH*8 + SCR_U2*16 + 2*TB*4*4)

// relayouted mid-cores: 126 * 4096 float4 = 8.25 MB device scratch
__device__ float4 c_relay[NSTEP * 4096];

extern __shared__ float smem_f[];

__device__ __forceinline__ uint64_t fma2(uint64_t a, uint64_t b, uint64_t c) {
    uint64_t d;
    asm("fma.rn.f32x2 %0, %1, %2, %3;" : "=l"(d) : "l"(a), "l"(b), "l"(c));
    return d;
}
__device__ __forceinline__ uint64_t mul2(uint64_t a, uint64_t b) {
    uint64_t d;
    asm("mul.rn.f32x2 %0, %1, %2;" : "=l"(d) : "l"(a), "l"(b));
    return d;
}
__device__ __forceinline__ uint64_t dup2(float f) {
    uint64_t d;
    asm("mov.b64 %0, {%1, %1};" : "=l"(d) : "f"(f));
    return d;
}
__device__ __forceinline__ uint64_t pack2(float a, float b) {
    uint64_t d;
    asm("mov.b64 %0, {%1, %2};" : "=l"(d) : "f"(a), "f"(b));
    return d;
}
__device__ __forceinline__ uint32_t smem_u32(const void* p) {
    return (uint32_t)__cvta_generic_to_shared(p);
}
__device__ __forceinline__ void cp_async16(uint32_t dst, const void* src) {
    asm volatile("cp.async.cg.shared.global [%0], [%1], 16;\n" :: "r"(dst), "l"(src));
}

// ---- pre-pass: re-tile mid_cores into c_relay (R15) ----
__global__ void __launch_bounds__(256)
relayout_kernel(const float* __restrict__ mc)
{
    int d = blockIdx.x * 256 + threadIdx.x;        // 0 .. 126*4096-1
    if (d >= NSTEP * 4096) return;
    int rp = d & 31;
    int ih = (d >> 5) & 1;
    int l  = (d >> 6) & 63;
    int s  = d >> 12;
    const float* src = mc + ((size_t)(s * 64 + l) * 4 + 2 * ih) * 64 + 2 * rp;
    c_relay[d] = make_float4(src[0], src[1], src[64], src[65]);
}

// Step body (R15 math): one LDS.128 per (l, ihalf) feeds 4 dup2 + 4P fma2.
template<int P>
__device__ __forceinline__ void step_body(
    const float4* __restrict__ CsL, const float2* __restrict__ vrow,
    const float* __restrict__ xrp,
    ulonglong2* __restrict__ scrW, int lane)
{
    uint64_t t[4][P][2];
    #pragma unroll
    for (int i = 0; i < 4; ++i)
        #pragma unroll
        for (int p = 0; p < P; ++p) { t[i][p][0] = 0ull; t[i][p][1] = 0ull; }

    #pragma unroll
    for (int h = 0; h < 8; ++h) {
        const int l2 = 2 * h;
        uint64_t vA[P], vB[P];
        #pragma unroll
        for (int p = 0; p < P; ++p) {
            ulonglong2 V = *(const ulonglong2*)(vrow + p * VPITCH + l2);
            vA[p] = V.x;                    // {v_a[l2],   v_b[l2]}
            vB[p] = V.y;                    // {v_a[l2+1], v_b[l2+1]}
        }
        #pragma unroll
        for (int li = 0; li < 2; ++li) {
            #pragma unroll
            for (int ih = 0; ih < 2; ++ih) {
                float4 c = CsL[((l2 + li) * 2 + ih) * 32];
                uint64_t c00 = dup2(c.x);
                uint64_t c01 = dup2(c.y);
                uint64_t c10 = dup2(c.z);
                uint64_t c11 = dup2(c.w);
                #pragma unroll
                for (int p = 0; p < P; ++p) {
                    uint64_t vv = li ? vB[p] : vA[p];
                    t[2*ih  ][p][0] = fma2(vv, c00, t[2*ih  ][p][0]);
                    t[2*ih  ][p][1] = fma2(vv, c01, t[2*ih  ][p][1]);
                    t[2*ih+1][p][0] = fma2(vv, c10, t[2*ih+1][p][0]);
                    t[2*ih+1][p][1] = fma2(vv, c11, t[2*ih+1][p][1]);
                }
            }
        }
    }

    // combine with x[., s+1, .] (broadcast LDS from the ring) and write partials
    #pragma unroll
    for (int p = 0; p < P; ++p) {
        float4 xa = *(const float4*)(xrp + p * 8);       // batch 2*(base+p)
        float4 xb = *(const float4*)(xrp + p * 8 + 4);   // batch 2*(base+p)+1
        uint64_t xp0 = pack2(xa.x, xb.x);
        uint64_t xp1 = pack2(xa.y, xb.y);
        uint64_t xp2 = pack2(xa.z, xb.z);
        uint64_t xp3 = pack2(xa.w, xb.w);
        uint64_t n0 = mul2(xp0, t[0][p][0]);
        n0 = fma2(xp1, t[1][p][0], n0);
        n0 = fma2(xp2, t[2][p][0], n0);
        n0 = fma2(xp3, t[3][p][0], n0);
        uint64_t n1 = mul2(xp0, t[0][p][1]);
        n1 = fma2(xp1, t[1][p][1], n1);
        n1 = fma2(xp2, t[2][p][1], n1);
        n1 = fma2(xp3, t[3][p][1], n1);
        ulonglong2 w; w.x = n0; w.y = n1;    // {va_r0,vb_r0},{va_r1,vb_r1}
        scrW[p * 32 + lane] = w;
    }
}

__global__ void __launch_bounds__(THREADS, 1)
tt_chain_kernel(const float* __restrict__ x,    // [B, 128, 4]
                const float* __restrict__ fc,   // [4, 64]
                const float* __restrict__ lc,   // [64, 4]
                float* __restrict__ out)        // [B, 1]
{
    float*      Cbuf = smem_f;
    float2*     vbuf = (float2*)(smem_f + 2*CSTEP);        // [14][VPITCH]
    ulonglong2* scr  = (ulonglong2*)(vbuf + NPAIR*VPITCH); // [2][4][14][32]
    float2*     scrf = (float2*)scr;                        // f2 view
    float2*     epi  = (float2*)scr;                        // parity-0 alias
    float*      xs   = (float*)(scr + SCR_U2);              // [2][TB][4]

    const float* mcr = (const float*)c_relay;

    const int tid  = threadIdx.x;
    const int warp = tid >> 5;
    const int lane = tid & 31;
    const int q    = warp & 3;             // l-quarter AND SMSP id
    const int sg   = warp >> 2;            // pair group 0,1,2
    const int Pw   = (sg < 2) ? 5 : 4;
    const int base = sg * 5;               // {0, 5, 10}; 10+4 = 14 pairs

    // ---- prefetch C[0]; stage x(site 1) into ring slot 1 ----
    {
        uint32_t dst = smem_u32(Cbuf);
        #pragma unroll
        for (int j = 0; j < 11; ++j) {
            int idx = j * THREADS + tid;           // 4096 16B chunks
            if (idx < 4096)
                cp_async16(dst + idx * 16, mcr + idx * 4);
        }
        if (tid < TB) {
            int gb = blockIdx.x * TB + tid;
            if (gb > BATCH - 1) gb = BATCH - 1;
            cp_async16(smem_u32(xs + 1 * (TB * 4) + tid * 4),
                       x + (size_t)gb * (LEN * 4) + 1 * 4);
        }
        asm volatile("cp.async.commit_group;\n");
    }

    // ---- prologue: fill this warp's vbuf slots with v0 (gmem x, one-time) ----
    #pragma unroll
    for (int v = 0; v < 3; ++v) {
        int slot = lane + 32 * v;          // 0..95 covers P*16 <= 80
        int pi = slot >> 4;
        int ro = slot & 15;
        if (pi < Pw) {
            int l = 16 * q + ro;
            int b0 = blockIdx.x * TB + 2 * (base + pi);
            int b1 = b0 + 1;
            if (b0 > BATCH - 1) b0 = BATCH - 1;
            if (b1 > BATCH - 1) b1 = BATCH - 1;
            float4 xA = *(const float4*)(x + (size_t)b0 * (LEN * 4));
            float4 xB = *(const float4*)(x + (size_t)b1 * (LEN * 4));
            float f0 = fc[l], f1 = fc[64 + l], f2 = fc[128 + l], f3 = fc[192 + l];
            float vx = f0*xA.x + f1*xA.y + f2*xA.z + f3*xA.w;
            float vy = f0*xB.x + f1*xB.y + f2*xB.z + f3*xB.w;
            vbuf[(base + pi) * VPITCH + l] = make_float2(vx, vy);
        }
    }
    asm volatile("cp.async.wait_group 0;\n");   // own C[0] + x(1) chunks landed

    // ---- main chain: ONE __syncthreads per step ----
    #pragma unroll 1
    for (int s = 0; s < NSTEP; ++s) {
        __syncthreads();   // C[s], x(s+1) visible; scr[(s-1)&1] complete; buffers free

        // C[s+1] prefetch + x(s+2) staging — single commit group at step head
        if (s + 1 < NSTEP) {
            uint32_t dst = smem_u32(Cbuf + ((s + 1) & 1) * CSTEP);
            const float* src = mcr + (size_t)(s + 1) * CSTEP;
            #pragma unroll
            for (int j = 0; j < 11; ++j) {
                int idx = j * THREADS + tid;
                if (idx < 4096)
                    cp_async16(dst + idx * 16, src + idx * 4);
            }
        }
        if (s + 2 <= LEN - 1 && tid < TB) {
            int gb = blockIdx.x * TB + tid;
            if (gb > BATCH - 1) gb = BATCH - 1;
            cp_async16(smem_u32(xs + ((s + 2) & 1) * (TB * 4) + tid * 4),
                       x + (size_t)gb * (LEN * 4) + (size_t)(s + 2) * 4);
        }
        asm volatile("cp.async.commit_group;\n");

        // finalize v_s into vbuf (warp-private slots), except s==0
        if (s > 0) {
            const int par = (s - 1) & 1;
            #pragma unroll
            for (int v = 0; v < 3; ++v) {
                int slot = lane + 32 * v;
                int pi = slot >> 4;
                int ro = slot & 15;
                if (pi < Pw) {
                    int pb = base + pi;
                    int l  = 16 * q + ro;
                    const float2* sp = scrf + (size_t)((par * 4) * NPAIR + pb) * 64 + l;
                    float2 a = sp[0];
                    float2 b = sp[NPAIR * 64];
                    float2 c = sp[2 * NPAIR * 64];
                    float2 d = sp[3 * NPAIR * 64];
                    vbuf[pb * VPITCH + l] =
                        make_float2((a.x + b.x) + (c.x + d.x),
                                    (a.y + b.y) + (c.y + d.y));
                }
            }
        }
        __syncwarp();

        const float4* CsL = (const float4*)(Cbuf + (s & 1) * CSTEP)
                          + (size_t)(1024 * q) + lane;
        const float2* vrow = vbuf + base * VPITCH + 16 * q;
        const float* xrp = xs + ((s + 1) & 1) * (TB * 4) + base * 8;
        ulonglong2* scrW = scr + (size_t)(((s & 1) * 4 + q) * NPAIR + base) * 32;

        if (Pw == 5) step_body<5>(CsL, vrow, xrp, scrW, lane);
        else         step_body<4>(CsL, vrow, xrp, scrW, lane);

        asm volatile("cp.async.wait_group 0;\n");   // own C[s+1] + x(s+2) landed
    }

    // ---- epilogue: v_126 in scr parity 1; dot with last-site vector ----
    __syncthreads();   // all scratch writes + x(127) staging visible
    {
        const int par = (NSTEP - 1) & 1;   // = 1
        const float* xr127 = xs + ((LEN - 1) & 1) * (TB * 4);
        #pragma unroll
        for (int v = 0; v < 3; ++v) {
            int slot = lane + 32 * v;
            int pi = slot >> 4;
            int ro = slot & 15;
            float2 contrib = make_float2(0.f, 0.f);
            int valid = (pi < Pw);
            int pb = base + (valid ? pi : 0);
            if (valid) {
                int l = 16 * q + ro;
                const float2* sp = scrf + (size_t)((par * 4) * NPAIR + pb) * 64 + l;
                float2 a = sp[0];
                float2 b = sp[NPAIR * 64];
                float2 c = sp[2 * NPAIR * 64];
                float2 d = sp[3 * NPAIR * 64];
                float vx = (a.x + b.x) + (c.x + d.x);
                float vy = (a.y + b.y) + (c.y + d.y);
                float4 l4  = *(const float4*)(lc + l * 4);
                float4 xe0 = *(const float4*)(xr127 + (2 * pb) * 4);
                float4 xe1 = *(const float4*)(xr127 + (2 * pb + 1) * 4);
                float lva = l4.x*xe0.x + l4.y*xe0.y + l4.z*xe0.z + l4.w*xe0.w;
                float lvb = l4.x*xe1.x + l4.y*xe1.y + l4.z*xe1.z + l4.w*xe1.w;
                contrib = make_float2(vx * lva, vy * lvb);
            }
            #pragma unroll
            for (int off = 8; off > 0; off >>= 1) {
                contrib.x += __shfl_down_sync(0xffffffffu, contrib.x, off, 16);
                contrib.y += __shfl_down_sync(0xffffffffu, contrib.y, off, 16);
            }
            __syncwarp();                      // par-1 reads done before epi (par-0) write
            if (ro == 0 && valid)
                epi[q * NPAIR + pb] = contrib;
        }
    }
    __syncthreads();
    if (tid < TB) {
        int b = blockIdx.x * TB + tid;
        if (b < BATCH) {
            int pb = tid >> 1;
            float sum = 0.f;
            #pragma unroll
            for (int qq = 0; qq < 4; ++qq) {
                float2 e = epi[qq * NPAIR + pb];
                sum += (tid & 1) ? e.y : e.x;
            }
            out[b] = sum;
        }
    }
}

extern "C" void kernel_launch(void* const* d_in, const int* in_sizes, int n_in,
                              void* d_out, int out_size) {
    const float* x  = (const float*)d_in[0];   // input_data [4096,128,4]
    const float* fc = (const float*)d_in[1];   // first_core [4,64]
    const float* mc = (const float*)d_in[2];   // mid_cores  [126,64,4,64]
    const float* lc = (const float*)d_in[3];   // last_core  [64,4]
    float* out = (float*)d_out;

    cudaFuncSetAttribute(tt_chain_kernel,
                         cudaFuncAttributeMaxDynamicSharedMemorySize, SMEM_BYTES);

    // pre-pass: re-tile mid_cores (8.25 MB, ~3 us)
    relayout_kernel<<<(NSTEP * 4096 + 255) / 256, 256>>>(mc);
    tt_chain_kernel<<<GRID, THREADS, SMEM_BYTES>>>(x, fc, lc, out);
}